// round 4
// baseline (speedup 1.0000x reference)
#include <cuda_runtime.h>

#define NB 64
#define LQ 256
#define EE 64
#define HH 64

// Scratch (static __device__ — no allocations allowed)
__device__ float g_vt[NB * LQ * EE];    // vt[n][l][k] = values[k][l][n]   (4 MB)
__device__ float g_attn[NB * EE * EE];  // attn[n][a][b]                   (1 MB)
__device__ float g_M[NB * EE * EE];     // M[n][e][k] = (W @ A_n)[e][k]    (1 MB)

// ---------------------------------------------------------------------------
// K0: transpose values[k][l][n] -> vt[n][l][k], one block per l
// ---------------------------------------------------------------------------
__global__ void __launch_bounds__(256) k_transpose(const float* __restrict__ values) {
    __shared__ float tile[64][65];
    const int l = blockIdx.x;
    const int tid = threadIdx.x;
#pragma unroll
    for (int i = 0; i < 4; i++) {
        int f = i * 256 + tid;          // float4 index 0..1023
        int k = f >> 4;                 // 0..63
        int n4 = f & 15;                // 0..15
        float4 v = *(const float4*)(values + ((k * LQ + l) * EE) + n4 * 4);
        tile[k][n4 * 4 + 0] = v.x;
        tile[k][n4 * 4 + 1] = v.y;
        tile[k][n4 * 4 + 2] = v.z;
        tile[k][n4 * 4 + 3] = v.w;
    }
    __syncthreads();
#pragma unroll
    for (int i = 0; i < 4; i++) {
        int f = i * 256 + tid;
        int nn = f >> 4;
        int k4 = f & 15;
        float4 v = make_float4(tile[k4 * 4 + 0][nn], tile[k4 * 4 + 1][nn],
                               tile[k4 * 4 + 2][nn], tile[k4 * 4 + 3][nn]);
        *(float4*)(g_vt + ((nn * LQ + l) * EE) + k4 * 4) = v;
    }
}

// ---------------------------------------------------------------------------
// K1: energy[a][b] = sum_l query[n,l,a]*keys[n,l,b]; softmax rows -> g_attn
// grid: 128 blocks = (n, half of the 64 a-rows)
// ---------------------------------------------------------------------------
__global__ void __launch_bounds__(256) k_attn(const float* __restrict__ query,
                                              const float* __restrict__ keys) {
    const int n = blockIdx.x >> 1;
    const int half = blockIdx.x & 1;
    __shared__ float sQ[32][32];   // [l'][a_local]
    __shared__ float sK[32][64];   // [l'][b]
    __shared__ float sE[32][68];
    const int tid = threadIdx.x;
    const int a0 = (tid >> 4) * 2;  // 0..30 step 2
    const int b0 = (tid & 15) * 4;  // 0..60 step 4

    float a00 = 0.f, a01 = 0.f, a02 = 0.f, a03 = 0.f;
    float a10 = 0.f, a11 = 0.f, a12 = 0.f, a13 = 0.f;

    for (int l0 = 0; l0 < LQ; l0 += 32) {
        {
            int lp = tid >> 3;  // 0..31
            int q4 = tid & 7;   // 0..7
            float4 v = *(const float4*)(query + ((n * LQ + l0 + lp) * EE) + half * 32 + q4 * 4);
            *(float4*)&sQ[lp][q4 * 4] = v;
        }
#pragma unroll
        for (int j = 0; j < 2; j++) {
            int f = j * 256 + tid;
            int lp = f >> 4;
            int b4 = f & 15;
            float4 v = *(const float4*)(keys + ((n * LQ + l0 + lp) * EE) + b4 * 4);
            *(float4*)&sK[lp][b4 * 4] = v;
        }
        __syncthreads();
#pragma unroll
        for (int lp = 0; lp < 32; lp++) {
            float2 qv = *(const float2*)&sQ[lp][a0];
            float4 kv = *(const float4*)&sK[lp][b0];
            a00 += qv.x * kv.x; a01 += qv.x * kv.y; a02 += qv.x * kv.z; a03 += qv.x * kv.w;
            a10 += qv.y * kv.x; a11 += qv.y * kv.y; a12 += qv.y * kv.z; a13 += qv.y * kv.w;
        }
        __syncthreads();
    }
    *(float4*)&sE[a0][b0]     = make_float4(a00, a01, a02, a03);
    *(float4*)&sE[a0 + 1][b0] = make_float4(a10, a11, a12, a13);
    __syncthreads();

    // softmax: 8 warps x 4 rows each (32 rows in this half); hd=1 so no scale
    const int w = tid >> 5, lane = tid & 31;
#pragma unroll
    for (int r = 0; r < 4; r++) {
        int row = w * 4 + r;
        float v0 = sE[row][lane];
        float v1 = sE[row][lane + 32];
        float m = fmaxf(v0, v1);
#pragma unroll
        for (int off = 16; off; off >>= 1) m = fmaxf(m, __shfl_xor_sync(0xffffffffu, m, off));
        float e0 = __expf(v0 - m);
        float e1 = __expf(v1 - m);
        float s = e0 + e1;
#pragma unroll
        for (int off = 16; off; off >>= 1) s += __shfl_xor_sync(0xffffffffu, s, off);
        float inv = 1.0f / s;
        float* dst = g_attn + (n * EE + half * 32 + row) * EE;
        dst[lane] = e0 * inv;
        dst[lane + 32] = e1 * inv;
    }
}

// ---------------------------------------------------------------------------
// K2: M_n[e][k] = sum_e' W[e][e'] * attn[n][e'][k]   (fold fc into attn)
// grid: 64 blocks (one per n)
// ---------------------------------------------------------------------------
__global__ void __launch_bounds__(256) k_M(const float* __restrict__ W) {
    const int n = blockIdx.x;
    __shared__ float sWt[64][68];  // sWt[e'][e] = W[e][e']
    __shared__ float sA[64][68];   // sA[e'][k]
    const int tid = threadIdx.x;
#pragma unroll
    for (int i = 0; i < 16; i++) {
        int idx = i * 256 + tid;
        int r = idx >> 6, c = idx & 63;
        sWt[c][r] = W[idx];                       // transpose W on the fly
        sA[r][c] = g_attn[n * 4096 + idx];
    }
    __syncthreads();
    const int e0 = (tid >> 4) * 4;
    const int k0 = (tid & 15) * 4;
    float acc[4][4] = {};
#pragma unroll
    for (int ep = 0; ep < 64; ep++) {
        float4 wv = *(const float4*)&sWt[ep][e0];
        float4 av = *(const float4*)&sA[ep][k0];
        acc[0][0] += wv.x * av.x; acc[0][1] += wv.x * av.y; acc[0][2] += wv.x * av.z; acc[0][3] += wv.x * av.w;
        acc[1][0] += wv.y * av.x; acc[1][1] += wv.y * av.y; acc[1][2] += wv.y * av.z; acc[1][3] += wv.y * av.w;
        acc[2][0] += wv.z * av.x; acc[2][1] += wv.z * av.y; acc[2][2] += wv.z * av.z; acc[2][3] += wv.z * av.w;
        acc[3][0] += wv.w * av.x; acc[3][1] += wv.w * av.y; acc[3][2] += wv.w * av.z; acc[3][3] += wv.w * av.w;
    }
#pragma unroll
    for (int i = 0; i < 4; i++) {
        *(float4*)(g_M + ((n * 64 + e0 + i) * 64) + k0) =
            make_float4(acc[i][0], acc[i][1], acc[i][2], acc[i][3]);
    }
}

// ---------------------------------------------------------------------------
// K3a: f[n,l,e] = b[e] + sum_k vt[n,l,k]*M_n[e,k]; LayerNorm over e;
//      writes ONLY the h=0 slice of out (4 MB). K3b broadcasts the rest.
// grid: 512 blocks = (n, 32-l chunk); 256 thr = 64 e-lanes x 4 l-lanes
// ---------------------------------------------------------------------------
__global__ void __launch_bounds__(256) k_compute(const float* __restrict__ bias,
                                                 const float* __restrict__ lnw,
                                                 const float* __restrict__ lnb,
                                                 float* __restrict__ out) {
    const int n = blockIdx.x >> 3;
    const int lc = blockIdx.x & 7;
    const int tid = threadIdx.x;
    const int e = tid & 63;
    const int ls = tid >> 6;

    __shared__ float sv[4][64];
    __shared__ float red[8][2];
    __shared__ float sb[64], sw[64], sbeta[64];
    if (tid < 64) {
        sb[tid] = bias[tid];
        sw[tid] = lnw[tid];
        sbeta[tid] = lnb[tid];
    }

    // cache this thread's M row in registers
    float Mreg[64];
    const float4* m4 = (const float4*)(g_M + (n * 64 + e) * 64);
#pragma unroll
    for (int j = 0; j < 16; j++) {
        float4 t = m4[j];
        Mreg[4 * j + 0] = t.x;
        Mreg[4 * j + 1] = t.y;
        Mreg[4 * j + 2] = t.z;
        Mreg[4 * j + 3] = t.w;
    }

    const int w = tid >> 5;

    for (int g = 0; g < 8; g++) {
        const int lbase = lc * 32 + g * 4;
        __syncthreads();  // protect sv/red from previous iteration readers
        sv[tid >> 6][tid & 63] = g_vt[(n * LQ + lbase + (tid >> 6)) * EE + (tid & 63)];
        __syncthreads();

        // 4 independent accumulators to break the FFMA RAW chain
        float p0 = 0.f, p1 = 0.f, p2 = 0.f, p3 = 0.f;
        const float4* v4 = (const float4*)sv[ls];
#pragma unroll
        for (int k4 = 0; k4 < 16; k4 += 4) {
            float4 va = v4[k4 + 0];
            float4 vb = v4[k4 + 1];
            float4 vc = v4[k4 + 2];
            float4 vd = v4[k4 + 3];
            p0 += va.x * Mreg[4 * k4 + 0] + va.y * Mreg[4 * k4 + 1]
                + va.z * Mreg[4 * k4 + 2] + va.w * Mreg[4 * k4 + 3];
            p1 += vb.x * Mreg[4 * k4 + 4] + vb.y * Mreg[4 * k4 + 5]
                + vb.z * Mreg[4 * k4 + 6] + vb.w * Mreg[4 * k4 + 7];
            p2 += vc.x * Mreg[4 * k4 + 8] + vc.y * Mreg[4 * k4 + 9]
                + vc.z * Mreg[4 * k4 + 10] + vc.w * Mreg[4 * k4 + 11];
            p3 += vd.x * Mreg[4 * k4 + 12] + vd.y * Mreg[4 * k4 + 13]
                + vd.z * Mreg[4 * k4 + 14] + vd.w * Mreg[4 * k4 + 15];
        }
        float acc = sb[e] + ((p0 + p1) + (p2 + p3));

        // LayerNorm reduction over the 64 e-lanes (2 warps per ls group)
        float s = acc, s2 = acc * acc;
#pragma unroll
        for (int off = 16; off; off >>= 1) {
            s += __shfl_xor_sync(0xffffffffu, s, off);
            s2 += __shfl_xor_sync(0xffffffffu, s2, off);
        }
        if ((tid & 31) == 0) {
            red[w][0] = s;
            red[w][1] = s2;
        }
        __syncthreads();
        float S = red[w][0] + red[w ^ 1][0];
        float S2 = red[w][1] + red[w ^ 1][1];
        float mu = S * (1.0f / 64.0f);
        float var = S2 * (1.0f / 64.0f) - mu * mu;
        float rinv = rsqrtf(var + 1e-5f);
        float y = (acc - mu) * rinv * sw[e] + sbeta[e];

        const int l = lbase + ls;
        out[(n * LQ + l) * EE + e] = y;   // h = 0 slice only
    }
}

// ---------------------------------------------------------------------------
// K3b: broadcast h=0 slice (4 MB) to h = 1..63.
// grid: 256 blocks, each owns a 16 KB contiguous segment held in registers.
// Warp stores are 512 B contiguous; 63*4 independent STG.128 per thread.
// ---------------------------------------------------------------------------
__global__ void __launch_bounds__(256) k_bcast(float* __restrict__ out) {
    const int tid = threadIdx.x;
    const size_t segOff4 = (size_t)blockIdx.x * 1024;  // float4 units (16KB/block)
    const float4* src = (const float4*)out + segOff4;
    float4 v0 = src[tid];
    float4 v1 = src[tid + 256];
    float4 v2 = src[tid + 512];
    float4 v3 = src[tid + 768];
    float4* dst = (float4*)out + segOff4 + tid;
    const size_t hstride4 = (size_t)NB * LQ * EE / 4;  // 262144 float4 = 4 MB
#pragma unroll 7
    for (int h = 1; h < HH; h++) {
        float4* p = dst + (size_t)h * hstride4;
        p[0] = v0;
        p[256] = v1;
        p[512] = v2;
        p[768] = v3;
    }
}

// ---------------------------------------------------------------------------
extern "C" void kernel_launch(void* const* d_in, const int* in_sizes, int n_in,
                              void* d_out, int out_size) {
    const float* values = (const float*)d_in[0];
    const float* keys   = (const float*)d_in[1];
    const float* query  = (const float*)d_in[2];
    const float* W      = (const float*)d_in[3];
    const float* b      = (const float*)d_in[4];
    const float* lnw    = (const float*)d_in[5];
    const float* lnb    = (const float*)d_in[6];
    float* out = (float*)d_out;

    k_transpose<<<256, 256>>>(values);
    k_attn<<<128, 256>>>(query, keys);
    k_M<<<64, 256>>>(W);
    k_compute<<<512, 256>>>(b, lnw, lnb, out);
    k_bcast<<<256, 256>>>(out);
}

// round 5
// speedup vs baseline: 1.1654x; 1.1654x over previous
#include <cuda_runtime.h>

#define NB 64
#define LQ 256
#define EE 64
#define HH 64

// Scratch (static __device__ — no allocations allowed)
__device__ float g_vt[NB * LQ * EE];    // vt[n][l][k] = values[k][l][n]   (4 MB)
__device__ float g_attn[NB * EE * EE];  // attn[n][a][b]                   (1 MB)
__device__ float g_M[NB * EE * EE];     // M[n][e][k] = (W @ A_n)[e][k]    (1 MB)

// ---------------------------------------------------------------------------
// K0: transpose values[k][l][n] -> vt[n][l][k], one block per l
// ---------------------------------------------------------------------------
__global__ void __launch_bounds__(256) k_transpose(const float* __restrict__ values) {
    __shared__ float tile[64][65];
    const int l = blockIdx.x;
    const int tid = threadIdx.x;
#pragma unroll
    for (int i = 0; i < 4; i++) {
        int f = i * 256 + tid;          // float4 index 0..1023
        int k = f >> 4;                 // 0..63
        int n4 = f & 15;                // 0..15
        float4 v = *(const float4*)(values + ((k * LQ + l) * EE) + n4 * 4);
        tile[k][n4 * 4 + 0] = v.x;
        tile[k][n4 * 4 + 1] = v.y;
        tile[k][n4 * 4 + 2] = v.z;
        tile[k][n4 * 4 + 3] = v.w;
    }
    __syncthreads();
#pragma unroll
    for (int i = 0; i < 4; i++) {
        int f = i * 256 + tid;
        int nn = f >> 4;
        int k4 = f & 15;
        float4 v = make_float4(tile[k4 * 4 + 0][nn], tile[k4 * 4 + 1][nn],
                               tile[k4 * 4 + 2][nn], tile[k4 * 4 + 3][nn]);
        *(float4*)(g_vt + ((nn * LQ + l) * EE) + k4 * 4) = v;
    }
}

// ---------------------------------------------------------------------------
// K1: energy[a][b] = sum_l query[n,l,a]*keys[n,l,b]; softmax rows -> g_attn
// grid: 128 blocks = (n, half of the 64 a-rows)
// ---------------------------------------------------------------------------
__global__ void __launch_bounds__(256) k_attn(const float* __restrict__ query,
                                              const float* __restrict__ keys) {
    const int n = blockIdx.x >> 1;
    const int half = blockIdx.x & 1;
    __shared__ float sQ[32][32];   // [l'][a_local]
    __shared__ float sK[32][64];   // [l'][b]
    __shared__ float sE[32][68];
    const int tid = threadIdx.x;
    const int a0 = (tid >> 4) * 2;  // 0..30 step 2
    const int b0 = (tid & 15) * 4;  // 0..60 step 4

    float a00 = 0.f, a01 = 0.f, a02 = 0.f, a03 = 0.f;
    float a10 = 0.f, a11 = 0.f, a12 = 0.f, a13 = 0.f;

    for (int l0 = 0; l0 < LQ; l0 += 32) {
        {
            int lp = tid >> 3;  // 0..31
            int q4 = tid & 7;   // 0..7
            float4 v = *(const float4*)(query + ((n * LQ + l0 + lp) * EE) + half * 32 + q4 * 4);
            *(float4*)&sQ[lp][q4 * 4] = v;
        }
#pragma unroll
        for (int j = 0; j < 2; j++) {
            int f = j * 256 + tid;
            int lp = f >> 4;
            int b4 = f & 15;
            float4 v = *(const float4*)(keys + ((n * LQ + l0 + lp) * EE) + b4 * 4);
            *(float4*)&sK[lp][b4 * 4] = v;
        }
        __syncthreads();
#pragma unroll
        for (int lp = 0; lp < 32; lp++) {
            float2 qv = *(const float2*)&sQ[lp][a0];
            float4 kv = *(const float4*)&sK[lp][b0];
            a00 += qv.x * kv.x; a01 += qv.x * kv.y; a02 += qv.x * kv.z; a03 += qv.x * kv.w;
            a10 += qv.y * kv.x; a11 += qv.y * kv.y; a12 += qv.y * kv.z; a13 += qv.y * kv.w;
        }
        __syncthreads();
    }
    *(float4*)&sE[a0][b0]     = make_float4(a00, a01, a02, a03);
    *(float4*)&sE[a0 + 1][b0] = make_float4(a10, a11, a12, a13);
    __syncthreads();

    // softmax: 8 warps x 4 rows each (32 rows in this half); hd=1 so no scale
    const int w = tid >> 5, lane = tid & 31;
#pragma unroll
    for (int r = 0; r < 4; r++) {
        int row = w * 4 + r;
        float v0 = sE[row][lane];
        float v1 = sE[row][lane + 32];
        float m = fmaxf(v0, v1);
#pragma unroll
        for (int off = 16; off; off >>= 1) m = fmaxf(m, __shfl_xor_sync(0xffffffffu, m, off));
        float e0 = __expf(v0 - m);
        float e1 = __expf(v1 - m);
        float s = e0 + e1;
#pragma unroll
        for (int off = 16; off; off >>= 1) s += __shfl_xor_sync(0xffffffffu, s, off);
        float inv = 1.0f / s;
        float* dst = g_attn + (n * EE + half * 32 + row) * EE;
        dst[lane] = e0 * inv;
        dst[lane + 32] = e1 * inv;
    }
}

// ---------------------------------------------------------------------------
// K2: M_n[e][k] = sum_e' W[e][e'] * attn[n][e'][k]   (fold fc into attn)
// grid: 64 blocks (one per n)
// ---------------------------------------------------------------------------
__global__ void __launch_bounds__(256) k_M(const float* __restrict__ W) {
    const int n = blockIdx.x;
    __shared__ float sWt[64][68];  // sWt[e'][e] = W[e][e']
    __shared__ float sA[64][68];   // sA[e'][k]
    const int tid = threadIdx.x;
#pragma unroll
    for (int i = 0; i < 16; i++) {
        int idx = i * 256 + tid;
        int r = idx >> 6, c = idx & 63;
        sWt[c][r] = W[idx];                       // transpose W on the fly
        sA[r][c] = g_attn[n * 4096 + idx];
    }
    __syncthreads();
    const int e0 = (tid >> 4) * 4;
    const int k0 = (tid & 15) * 4;
    float acc[4][4] = {};
#pragma unroll
    for (int ep = 0; ep < 64; ep++) {
        float4 wv = *(const float4*)&sWt[ep][e0];
        float4 av = *(const float4*)&sA[ep][k0];
        acc[0][0] += wv.x * av.x; acc[0][1] += wv.x * av.y; acc[0][2] += wv.x * av.z; acc[0][3] += wv.x * av.w;
        acc[1][0] += wv.y * av.x; acc[1][1] += wv.y * av.y; acc[1][2] += wv.y * av.z; acc[1][3] += wv.y * av.w;
        acc[2][0] += wv.z * av.x; acc[2][1] += wv.z * av.y; acc[2][2] += wv.z * av.z; acc[2][3] += wv.z * av.w;
        acc[3][0] += wv.w * av.x; acc[3][1] += wv.w * av.y; acc[3][2] += wv.w * av.z; acc[3][3] += wv.w * av.w;
    }
#pragma unroll
    for (int i = 0; i < 4; i++) {
        *(float4*)(g_M + ((n * 64 + e0 + i) * 64) + k0) =
            make_float4(acc[i][0], acc[i][1], acc[i][2], acc[i][3]);
    }
}

// ---------------------------------------------------------------------------
// K3: fused GEMV + LayerNorm + 64-way broadcast write.
//   Y[l][e] = LN_e( b[e] + sum_k vt[n,l,k] * M_n[e,k] )  for a 32-l tile,
//   staged in smem, then written to all 64 h copies with coalesced STG.128.
// grid: 512 blocks = (n, 32-l chunk); 256 threads = (16 l-pairs) x (16 e-quads)
// ---------------------------------------------------------------------------
__global__ void __launch_bounds__(256) k_out(const float* __restrict__ bias,
                                             const float* __restrict__ lnw,
                                             const float* __restrict__ lnb,
                                             float* __restrict__ out) {
    const int n = blockIdx.x >> 3;
    const int lc = blockIdx.x & 7;
    const int tid = threadIdx.x;

    __shared__ float sMt[64][68];   // sMt[k][e] = M_n[e][k]
    __shared__ float sv[32][68];    // sv[l'][k]
    __shared__ float sy[32][64];    // normalized output tile
    __shared__ float sb[64], sw[64], sbeta[64];

    if (tid < 64) {
        sb[tid] = bias[tid];
        sw[tid] = lnw[tid];
        sbeta[tid] = lnb[tid];
    }

    // Load + transpose M_n (64x64) into sMt[k][e]
    const float* Mn = g_M + n * 4096;
#pragma unroll
    for (int i = 0; i < 16; i++) {
        int idx = i * 256 + tid;
        int e = idx >> 6, k = idx & 63;
        sMt[k][e] = Mn[idx];
    }
    // Load vt tile (32 x 64), coalesced
    const int lbase = lc * 32;
    const float* vtn = g_vt + (n * LQ + lbase) * EE;
#pragma unroll
    for (int i = 0; i < 8; i++) {
        int idx = i * 256 + tid;
        sv[idx >> 6][idx & 63] = vtn[idx];
    }
    __syncthreads();

    // Micro-tile: 2 l-rows x 4 e-cols per thread
    const int r0 = (tid >> 4) * 2;   // 0..30
    const int e0 = (tid & 15) * 4;   // 0..60

    float a00 = 0.f, a01 = 0.f, a02 = 0.f, a03 = 0.f;
    float a10 = 0.f, a11 = 0.f, a12 = 0.f, a13 = 0.f;
#pragma unroll
    for (int k = 0; k < 64; k++) {
        float v0 = sv[r0][k];
        float v1 = sv[r0 + 1][k];
        float4 m = *(const float4*)&sMt[k][e0];
        a00 += v0 * m.x; a01 += v0 * m.y; a02 += v0 * m.z; a03 += v0 * m.w;
        a10 += v1 * m.x; a11 += v1 * m.y; a12 += v1 * m.z; a13 += v1 * m.w;
    }
    // add fc bias before LN
    float b0v = sb[e0], b1v = sb[e0 + 1], b2v = sb[e0 + 2], b3v = sb[e0 + 3];
    a00 += b0v; a01 += b1v; a02 += b2v; a03 += b3v;
    a10 += b0v; a11 += b1v; a12 += b2v; a13 += b3v;

    // LN stats: reduce over the 16 lanes that share a row-pair (offsets 1..8)
    float s0 = (a00 + a01) + (a02 + a03);
    float q0 = (a00 * a00 + a01 * a01) + (a02 * a02 + a03 * a03);
    float s1 = (a10 + a11) + (a12 + a13);
    float q1 = (a10 * a10 + a11 * a11) + (a12 * a12 + a13 * a13);
#pragma unroll
    for (int off = 8; off; off >>= 1) {
        s0 += __shfl_xor_sync(0xffffffffu, s0, off);
        q0 += __shfl_xor_sync(0xffffffffu, q0, off);
        s1 += __shfl_xor_sync(0xffffffffu, s1, off);
        q1 += __shfl_xor_sync(0xffffffffu, q1, off);
    }
    float mu0 = s0 * (1.0f / 64.0f);
    float var0 = q0 * (1.0f / 64.0f) - mu0 * mu0;
    float ri0 = rsqrtf(var0 + 1e-5f);
    float mu1 = s1 * (1.0f / 64.0f);
    float var1 = q1 * (1.0f / 64.0f) - mu1 * mu1;
    float ri1 = rsqrtf(var1 + 1e-5f);

    float w0 = sw[e0], w1 = sw[e0 + 1], w2 = sw[e0 + 2], w3 = sw[e0 + 3];
    float g0 = sbeta[e0], g1 = sbeta[e0 + 1], g2 = sbeta[e0 + 2], g3 = sbeta[e0 + 3];

    *(float4*)&sy[r0][e0] = make_float4((a00 - mu0) * ri0 * w0 + g0,
                                        (a01 - mu0) * ri0 * w1 + g1,
                                        (a02 - mu0) * ri0 * w2 + g2,
                                        (a03 - mu0) * ri0 * w3 + g3);
    *(float4*)&sy[r0 + 1][e0] = make_float4((a10 - mu1) * ri1 * w0 + g0,
                                            (a11 - mu1) * ri1 * w1 + g1,
                                            (a12 - mu1) * ri1 * w2 + g2,
                                            (a13 - mu1) * ri1 * w3 + g3);
    __syncthreads();

    // Broadcast phase: 64 h-copies of the 8KB tile, coalesced STG.128
    const float4* sy4 = (const float4*)sy;
    float4 v0 = sy4[tid];
    float4 v1 = sy4[tid + 256];
    float4* dst = (float4*)out + n * 4096 + lc * 512 + tid;
    const size_t hstride4 = (size_t)NB * LQ * EE / 4;  // 262144 float4 = 4 MB
#pragma unroll 8
    for (int h = 0; h < HH; h++) {
        dst[0] = v0;
        dst[256] = v1;
        dst += hstride4;
    }
}

// ---------------------------------------------------------------------------
extern "C" void kernel_launch(void* const* d_in, const int* in_sizes, int n_in,
                              void* d_out, int out_size) {
    const float* values = (const float*)d_in[0];
    const float* keys   = (const float*)d_in[1];
    const float* query  = (const float*)d_in[2];
    const float* W      = (const float*)d_in[3];
    const float* b      = (const float*)d_in[4];
    const float* lnw    = (const float*)d_in[5];
    const float* lnb    = (const float*)d_in[6];
    float* out = (float*)d_out;

    k_transpose<<<256, 256>>>(values);
    k_attn<<<128, 256>>>(query, keys);
    k_M<<<64, 256>>>(W);
    k_out<<<512, 256>>>(b, lnw, lnb, out);
}

// round 6
// speedup vs baseline: 1.2183x; 1.0454x over previous
#include <cuda_runtime.h>

#define NB 64
#define LQ 256
#define EE 64
#define HH 64

// Scratch (static __device__ — no allocations allowed)
__device__ float g_vt[NB * LQ * EE];    // vt[n][l][k] = values[k][l][n]   (4 MB)
__device__ float g_attn[NB * EE * EE];  // attn[n][a][b]                   (1 MB)
__device__ float g_M[NB * EE * EE];     // M[n][e][k] = (W @ A_n)[e][k]    (1 MB)

// ---------------------------------------------------------------------------
// K_front: merged launch.
//   blocks [0,256):   transpose values[k][l][n] -> vt[n][l][k]   (one per l)
//   blocks [256,384): energy Q·K^T + softmax -> g_attn           (n, half)
// ---------------------------------------------------------------------------
__global__ void __launch_bounds__(256) k_front(const float* __restrict__ values,
                                               const float* __restrict__ query,
                                               const float* __restrict__ keys) {
    __shared__ float sh[5248];           // aliased pool (max of both phases)
    const int tid = threadIdx.x;

    if (blockIdx.x < 256) {
        // ---- transpose phase ----
        float (*tile)[65] = (float(*)[65])sh;
        const int l = blockIdx.x;
#pragma unroll
        for (int i = 0; i < 4; i++) {
            int f = i * 256 + tid;          // float4 index 0..1023
            int k = f >> 4;                 // 0..63
            int n4 = f & 15;                // 0..15
            float4 v = *(const float4*)(values + ((k * LQ + l) * EE) + n4 * 4);
            tile[k][n4 * 4 + 0] = v.x;
            tile[k][n4 * 4 + 1] = v.y;
            tile[k][n4 * 4 + 2] = v.z;
            tile[k][n4 * 4 + 3] = v.w;
        }
        __syncthreads();
#pragma unroll
        for (int i = 0; i < 4; i++) {
            int f = i * 256 + tid;
            int nn = f >> 4;
            int k4 = f & 15;
            float4 v = make_float4(tile[k4 * 4 + 0][nn], tile[k4 * 4 + 1][nn],
                                   tile[k4 * 4 + 2][nn], tile[k4 * 4 + 3][nn]);
            *(float4*)(g_vt + ((nn * LQ + l) * EE) + k4 * 4) = v;
        }
        return;
    }

    // ---- attention phase ----
    const int bb = blockIdx.x - 256;
    const int n = bb >> 1;
    const int half = bb & 1;
    float (*sQ)[32] = (float(*)[32])sh;            // [l'][a_local]  1024
    float (*sK)[64] = (float(*)[64])(sh + 1024);   // [l'][b]        2048
    float (*sE)[68] = (float(*)[68])(sh + 3072);   // energy         2176
    const int a0 = (tid >> 4) * 2;  // 0..30 step 2
    const int b0 = (tid & 15) * 4;  // 0..60 step 4

    float a00 = 0.f, a01 = 0.f, a02 = 0.f, a03 = 0.f;
    float a10 = 0.f, a11 = 0.f, a12 = 0.f, a13 = 0.f;

    for (int l0 = 0; l0 < LQ; l0 += 32) {
        {
            int lp = tid >> 3;  // 0..31
            int q4 = tid & 7;   // 0..7
            float4 v = *(const float4*)(query + ((n * LQ + l0 + lp) * EE) + half * 32 + q4 * 4);
            *(float4*)&sQ[lp][q4 * 4] = v;
        }
#pragma unroll
        for (int j = 0; j < 2; j++) {
            int f = j * 256 + tid;
            int lp = f >> 4;
            int b4 = f & 15;
            float4 v = *(const float4*)(keys + ((n * LQ + l0 + lp) * EE) + b4 * 4);
            *(float4*)&sK[lp][b4 * 4] = v;
        }
        __syncthreads();
#pragma unroll
        for (int lp = 0; lp < 32; lp++) {
            float2 qv = *(const float2*)&sQ[lp][a0];
            float4 kv = *(const float4*)&sK[lp][b0];
            a00 += qv.x * kv.x; a01 += qv.x * kv.y; a02 += qv.x * kv.z; a03 += qv.x * kv.w;
            a10 += qv.y * kv.x; a11 += qv.y * kv.y; a12 += qv.y * kv.z; a13 += qv.y * kv.w;
        }
        __syncthreads();
    }
    *(float4*)&sE[a0][b0]     = make_float4(a00, a01, a02, a03);
    *(float4*)&sE[a0 + 1][b0] = make_float4(a10, a11, a12, a13);
    __syncthreads();

    // softmax: 8 warps x 4 rows each (32 rows in this half); hd=1 so no scale
    const int w = tid >> 5, lane = tid & 31;
#pragma unroll
    for (int r = 0; r < 4; r++) {
        int row = w * 4 + r;
        float v0 = sE[row][lane];
        float v1 = sE[row][lane + 32];
        float m = fmaxf(v0, v1);
#pragma unroll
        for (int off = 16; off; off >>= 1) m = fmaxf(m, __shfl_xor_sync(0xffffffffu, m, off));
        float e0 = __expf(v0 - m);
        float e1 = __expf(v1 - m);
        float s = e0 + e1;
#pragma unroll
        for (int off = 16; off; off >>= 1) s += __shfl_xor_sync(0xffffffffu, s, off);
        float inv = 1.0f / s;
        float* dst = g_attn + (n * EE + half * 32 + row) * EE;
        dst[lane] = e0 * inv;
        dst[lane + 32] = e1 * inv;
    }
}

// ---------------------------------------------------------------------------
// K2: M_n[e][k] = sum_e' W[e][e'] * attn[n][e'][k]   (fold fc into attn)
// grid: 64 blocks (one per n)
// ---------------------------------------------------------------------------
__global__ void __launch_bounds__(256) k_M(const float* __restrict__ W) {
    const int n = blockIdx.x;
    __shared__ float sWt[64][68];  // sWt[e'][e] = W[e][e']
    __shared__ float sA[64][68];   // sA[e'][k]
    const int tid = threadIdx.x;
#pragma unroll
    for (int i = 0; i < 16; i++) {
        int idx = i * 256 + tid;
        int r = idx >> 6, c = idx & 63;
        sWt[c][r] = W[idx];                       // transpose W on the fly
        sA[r][c] = g_attn[n * 4096 + idx];
    }
    __syncthreads();
    const int e0 = (tid >> 4) * 4;
    const int k0 = (tid & 15) * 4;
    float acc[4][4] = {};
#pragma unroll
    for (int ep = 0; ep < 64; ep++) {
        float4 wv = *(const float4*)&sWt[ep][e0];
        float4 av = *(const float4*)&sA[ep][k0];
        acc[0][0] += wv.x * av.x; acc[0][1] += wv.x * av.y; acc[0][2] += wv.x * av.z; acc[0][3] += wv.x * av.w;
        acc[1][0] += wv.y * av.x; acc[1][1] += wv.y * av.y; acc[1][2] += wv.y * av.z; acc[1][3] += wv.y * av.w;
        acc[2][0] += wv.z * av.x; acc[2][1] += wv.z * av.y; acc[2][2] += wv.z * av.z; acc[2][3] += wv.z * av.w;
        acc[3][0] += wv.w * av.x; acc[3][1] += wv.w * av.y; acc[3][2] += wv.w * av.z; acc[3][3] += wv.w * av.w;
    }
#pragma unroll
    for (int i = 0; i < 4; i++) {
        *(float4*)(g_M + ((n * 64 + e0 + i) * 64) + k0) =
            make_float4(acc[i][0], acc[i][1], acc[i][2], acc[i][3]);
    }
}

// ---------------------------------------------------------------------------
// K3: tiled GEMV + LayerNorm; writes ONLY the h=0 slice (4 MB).
// grid: 512 blocks = (n, 32-l chunk); 256 threads = (16 l-pairs) x (16 e-quads)
// ---------------------------------------------------------------------------
__global__ void __launch_bounds__(256) k_compute(const float* __restrict__ bias,
                                                 const float* __restrict__ lnw,
                                                 const float* __restrict__ lnb,
                                                 float* __restrict__ out) {
    const int n = blockIdx.x >> 3;
    const int lc = blockIdx.x & 7;
    const int tid = threadIdx.x;

    __shared__ float sMt[64][68];   // sMt[k][e] = M_n[e][k]
    __shared__ float sv[32][68];    // sv[l'][k]
    __shared__ float sy[32][64];    // normalized output tile
    __shared__ float sb[64], sw[64], sbeta[64];

    if (tid < 64) {
        sb[tid] = bias[tid];
        sw[tid] = lnw[tid];
        sbeta[tid] = lnb[tid];
    }

    // Load + transpose M_n (64x64) into sMt[k][e]
    const float* Mn = g_M + n * 4096;
#pragma unroll
    for (int i = 0; i < 16; i++) {
        int idx = i * 256 + tid;
        int e = idx >> 6, k = idx & 63;
        sMt[k][e] = Mn[idx];
    }
    // Load vt tile (32 x 64), coalesced
    const int lbase = lc * 32;
    const float* vtn = g_vt + (n * LQ + lbase) * EE;
#pragma unroll
    for (int i = 0; i < 8; i++) {
        int idx = i * 256 + tid;
        sv[idx >> 6][idx & 63] = vtn[idx];
    }
    __syncthreads();

    // Micro-tile: 2 l-rows x 4 e-cols per thread
    const int r0 = (tid >> 4) * 2;   // 0..30
    const int e0 = (tid & 15) * 4;   // 0..60

    float a00 = 0.f, a01 = 0.f, a02 = 0.f, a03 = 0.f;
    float a10 = 0.f, a11 = 0.f, a12 = 0.f, a13 = 0.f;
#pragma unroll
    for (int k = 0; k < 64; k++) {
        float v0 = sv[r0][k];
        float v1 = sv[r0 + 1][k];
        float4 m = *(const float4*)&sMt[k][e0];
        a00 += v0 * m.x; a01 += v0 * m.y; a02 += v0 * m.z; a03 += v0 * m.w;
        a10 += v1 * m.x; a11 += v1 * m.y; a12 += v1 * m.z; a13 += v1 * m.w;
    }
    // add fc bias before LN
    float b0v = sb[e0], b1v = sb[e0 + 1], b2v = sb[e0 + 2], b3v = sb[e0 + 3];
    a00 += b0v; a01 += b1v; a02 += b2v; a03 += b3v;
    a10 += b0v; a11 += b1v; a12 += b2v; a13 += b3v;

    // LN stats: reduce over the 16 lanes that share a row-pair (offsets 1..8)
    float s0 = (a00 + a01) + (a02 + a03);
    float q0 = (a00 * a00 + a01 * a01) + (a02 * a02 + a03 * a03);
    float s1 = (a10 + a11) + (a12 + a13);
    float q1 = (a10 * a10 + a11 * a11) + (a12 * a12 + a13 * a13);
#pragma unroll
    for (int off = 8; off; off >>= 1) {
        s0 += __shfl_xor_sync(0xffffffffu, s0, off);
        q0 += __shfl_xor_sync(0xffffffffu, q0, off);
        s1 += __shfl_xor_sync(0xffffffffu, s1, off);
        q1 += __shfl_xor_sync(0xffffffffu, q1, off);
    }
    float mu0 = s0 * (1.0f / 64.0f);
    float var0 = q0 * (1.0f / 64.0f) - mu0 * mu0;
    float ri0 = rsqrtf(var0 + 1e-5f);
    float mu1 = s1 * (1.0f / 64.0f);
    float var1 = q1 * (1.0f / 64.0f) - mu1 * mu1;
    float ri1 = rsqrtf(var1 + 1e-5f);

    float w0 = sw[e0], w1 = sw[e0 + 1], w2 = sw[e0 + 2], w3 = sw[e0 + 3];
    float g0 = sbeta[e0], g1 = sbeta[e0 + 1], g2 = sbeta[e0 + 2], g3 = sbeta[e0 + 3];

    *(float4*)&sy[r0][e0] = make_float4((a00 - mu0) * ri0 * w0 + g0,
                                        (a01 - mu0) * ri0 * w1 + g1,
                                        (a02 - mu0) * ri0 * w2 + g2,
                                        (a03 - mu0) * ri0 * w3 + g3);
    *(float4*)&sy[r0 + 1][e0] = make_float4((a10 - mu1) * ri1 * w0 + g0,
                                            (a11 - mu1) * ri1 * w1 + g1,
                                            (a12 - mu1) * ri1 * w2 + g2,
                                            (a13 - mu1) * ri1 * w3 + g3);
    __syncthreads();

    // write h = 0 slice only (coalesced STG.128)
    const float4* sy4 = (const float4*)sy;
    float4* dst = (float4*)out + n * 4096 + lc * 512 + tid;
    dst[0] = sy4[tid];
    dst[256] = sy4[tid + 256];
}

// ---------------------------------------------------------------------------
// K4: broadcast h=0 slice (4 MB) to h = 1..63 (252 MB of streaming writes).
// grid: 256 blocks, each owns a 16 KB contiguous segment held in registers.
// ---------------------------------------------------------------------------
__global__ void __launch_bounds__(256) k_bcast(float* __restrict__ out) {
    const int tid = threadIdx.x;
    const size_t segOff4 = (size_t)blockIdx.x * 1024;  // float4 units (16KB/block)
    const float4* src = (const float4*)out + segOff4;
    float4 v0 = src[tid];
    float4 v1 = src[tid + 256];
    float4 v2 = src[tid + 512];
    float4 v3 = src[tid + 768];
    float4* dst = (float4*)out + segOff4 + tid;
    const size_t hstride4 = (size_t)NB * LQ * EE / 4;  // 262144 float4 = 4 MB
#pragma unroll 7
    for (int h = 1; h < HH; h++) {
        float4* p = dst + (size_t)h * hstride4;
        __stcs(p, v0);
        __stcs(p + 256, v1);
        __stcs(p + 512, v2);
        __stcs(p + 768, v3);
    }
}

// ---------------------------------------------------------------------------
extern "C" void kernel_launch(void* const* d_in, const int* in_sizes, int n_in,
                              void* d_out, int out_size) {
    const float* values = (const float*)d_in[0];
    const float* keys   = (const float*)d_in[1];
    const float* query  = (const float*)d_in[2];
    const float* W      = (const float*)d_in[3];
    const float* b      = (const float*)d_in[4];
    const float* lnw    = (const float*)d_in[5];
    const float* lnb    = (const float*)d_in[6];
    float* out = (float*)d_out;

    k_front<<<384, 256>>>(values, query, keys);
    k_M<<<64, 256>>>(W);
    k_compute<<<512, 256>>>(b, lnw, lnb, out);
    k_bcast<<<256, 256>>>(out);
}

// round 7
// speedup vs baseline: 1.2220x; 1.0030x over previous
#include <cuda_runtime.h>

#define NB 64
#define LQ 256
#define EE 64
#define HH 64

// Scratch (static __device__ — no allocations allowed)
__device__ float g_vt[NB * LQ * EE];    // vt[n][l][k] = values[k][l][n]   (4 MB)
__device__ float g_attn[NB * EE * EE];  // attn[n][a][b]                   (1 MB)
__device__ float g_M[NB * EE * EE];     // M[n][e][k] = (W @ A_n)[e][k]    (1 MB)

// ---------------------------------------------------------------------------
// K_front: merged launch.
//   blocks [0,256):   transpose values[k][l][n] -> vt[n][l][k]   (one per l)
//   blocks [256,384): energy Q·K^T + softmax -> g_attn           (n, half)
// ---------------------------------------------------------------------------
__global__ void __launch_bounds__(256) k_front(const float* __restrict__ values,
                                               const float* __restrict__ query,
                                               const float* __restrict__ keys) {
    __shared__ float sh[5248];           // aliased pool (max of both phases)
    const int tid = threadIdx.x;

    if (blockIdx.x < 256) {
        // ---- transpose phase ----
        float (*tile)[65] = (float(*)[65])sh;
        const int l = blockIdx.x;
#pragma unroll
        for (int i = 0; i < 4; i++) {
            int f = i * 256 + tid;          // float4 index 0..1023
            int k = f >> 4;                 // 0..63
            int n4 = f & 15;                // 0..15
            float4 v = *(const float4*)(values + ((k * LQ + l) * EE) + n4 * 4);
            tile[k][n4 * 4 + 0] = v.x;
            tile[k][n4 * 4 + 1] = v.y;
            tile[k][n4 * 4 + 2] = v.z;
            tile[k][n4 * 4 + 3] = v.w;
        }
        __syncthreads();
#pragma unroll
        for (int i = 0; i < 4; i++) {
            int f = i * 256 + tid;
            int nn = f >> 4;
            int k4 = f & 15;
            float4 v = make_float4(tile[k4 * 4 + 0][nn], tile[k4 * 4 + 1][nn],
                                   tile[k4 * 4 + 2][nn], tile[k4 * 4 + 3][nn]);
            *(float4*)(g_vt + ((nn * LQ + l) * EE) + k4 * 4) = v;
        }
        return;
    }

    // ---- attention phase ----
    const int bb = blockIdx.x - 256;
    const int n = bb >> 1;
    const int half = bb & 1;
    float (*sQ)[32] = (float(*)[32])sh;            // [l'][a_local]  1024
    float (*sK)[64] = (float(*)[64])(sh + 1024);   // [l'][b]        2048
    float (*sE)[68] = (float(*)[68])(sh + 3072);   // energy         2176
    const int a0 = (tid >> 4) * 2;  // 0..30 step 2
    const int b0 = (tid & 15) * 4;  // 0..60 step 4

    float a00 = 0.f, a01 = 0.f, a02 = 0.f, a03 = 0.f;
    float a10 = 0.f, a11 = 0.f, a12 = 0.f, a13 = 0.f;

    for (int l0 = 0; l0 < LQ; l0 += 32) {
        {
            int lp = tid >> 3;  // 0..31
            int q4 = tid & 7;   // 0..7
            float4 v = *(const float4*)(query + ((n * LQ + l0 + lp) * EE) + half * 32 + q4 * 4);
            *(float4*)&sQ[lp][q4 * 4] = v;
        }
#pragma unroll
        for (int j = 0; j < 2; j++) {
            int f = j * 256 + tid;
            int lp = f >> 4;
            int b4 = f & 15;
            float4 v = *(const float4*)(keys + ((n * LQ + l0 + lp) * EE) + b4 * 4);
            *(float4*)&sK[lp][b4 * 4] = v;
        }
        __syncthreads();
#pragma unroll
        for (int lp = 0; lp < 32; lp++) {
            float2 qv = *(const float2*)&sQ[lp][a0];
            float4 kv = *(const float4*)&sK[lp][b0];
            a00 += qv.x * kv.x; a01 += qv.x * kv.y; a02 += qv.x * kv.z; a03 += qv.x * kv.w;
            a10 += qv.y * kv.x; a11 += qv.y * kv.y; a12 += qv.y * kv.z; a13 += qv.y * kv.w;
        }
        __syncthreads();
    }
    *(float4*)&sE[a0][b0]     = make_float4(a00, a01, a02, a03);
    *(float4*)&sE[a0 + 1][b0] = make_float4(a10, a11, a12, a13);
    __syncthreads();

    // softmax: 8 warps x 4 rows each (32 rows in this half); hd=1 so no scale
    const int w = tid >> 5, lane = tid & 31;
#pragma unroll
    for (int r = 0; r < 4; r++) {
        int row = w * 4 + r;
        float v0 = sE[row][lane];
        float v1 = sE[row][lane + 32];
        float m = fmaxf(v0, v1);
#pragma unroll
        for (int off = 16; off; off >>= 1) m = fmaxf(m, __shfl_xor_sync(0xffffffffu, m, off));
        float e0 = __expf(v0 - m);
        float e1 = __expf(v1 - m);
        float s = e0 + e1;
#pragma unroll
        for (int off = 16; off; off >>= 1) s += __shfl_xor_sync(0xffffffffu, s, off);
        float inv = 1.0f / s;
        float* dst = g_attn + (n * EE + half * 32 + row) * EE;
        dst[lane] = e0 * inv;
        dst[lane + 32] = e1 * inv;
    }
}

// ---------------------------------------------------------------------------
// K2: M_n[e][k] = sum_e' W[e][e'] * attn[n][e'][k]   (fold fc into attn)
// grid: 64 blocks (one per n)
// ---------------------------------------------------------------------------
__global__ void __launch_bounds__(256) k_M(const float* __restrict__ W) {
    const int n = blockIdx.x;
    __shared__ float sWt[64][68];  // sWt[e'][e] = W[e][e']
    __shared__ float sA[64][68];   // sA[e'][k]
    const int tid = threadIdx.x;
#pragma unroll
    for (int i = 0; i < 16; i++) {
        int idx = i * 256 + tid;
        int r = idx >> 6, c = idx & 63;
        sWt[c][r] = W[idx];                       // transpose W on the fly
        sA[r][c] = g_attn[n * 4096 + idx];
    }
    __syncthreads();
    const int e0 = (tid >> 4) * 4;
    const int k0 = (tid & 15) * 4;
    float acc[4][4] = {};
#pragma unroll
    for (int ep = 0; ep < 64; ep++) {
        float4 wv = *(const float4*)&sWt[ep][e0];
        float4 av = *(const float4*)&sA[ep][k0];
        acc[0][0] += wv.x * av.x; acc[0][1] += wv.x * av.y; acc[0][2] += wv.x * av.z; acc[0][3] += wv.x * av.w;
        acc[1][0] += wv.y * av.x; acc[1][1] += wv.y * av.y; acc[1][2] += wv.y * av.z; acc[1][3] += wv.y * av.w;
        acc[2][0] += wv.z * av.x; acc[2][1] += wv.z * av.y; acc[2][2] += wv.z * av.z; acc[2][3] += wv.z * av.w;
        acc[3][0] += wv.w * av.x; acc[3][1] += wv.w * av.y; acc[3][2] += wv.w * av.z; acc[3][3] += wv.w * av.w;
    }
#pragma unroll
    for (int i = 0; i < 4; i++) {
        *(float4*)(g_M + ((n * 64 + e0 + i) * 64) + k0) =
            make_float4(acc[i][0], acc[i][1], acc[i][2], acc[i][3]);
    }
}

// ---------------------------------------------------------------------------
// K3: tiled GEMV + LayerNorm; writes ONLY the h=0 slice (4 MB).
// grid: 512 blocks = (n, 32-l chunk); 256 threads = (16 l-pairs) x (16 e-quads)
// ---------------------------------------------------------------------------
__global__ void __launch_bounds__(256) k_compute(const float* __restrict__ bias,
                                                 const float* __restrict__ lnw,
                                                 const float* __restrict__ lnb,
                                                 float* __restrict__ out) {
    const int n = blockIdx.x >> 3;
    const int lc = blockIdx.x & 7;
    const int tid = threadIdx.x;

    __shared__ float sMt[64][68];   // sMt[k][e] = M_n[e][k]
    __shared__ float sv[32][68];    // sv[l'][k]
    __shared__ float sy[32][64];    // normalized output tile
    __shared__ float sb[64], sw[64], sbeta[64];

    if (tid < 64) {
        sb[tid] = bias[tid];
        sw[tid] = lnw[tid];
        sbeta[tid] = lnb[tid];
    }

    // Load + transpose M_n (64x64) into sMt[k][e]
    const float* Mn = g_M + n * 4096;
#pragma unroll
    for (int i = 0; i < 16; i++) {
        int idx = i * 256 + tid;
        int e = idx >> 6, k = idx & 63;
        sMt[k][e] = Mn[idx];
    }
    // Load vt tile (32 x 64), coalesced
    const int lbase = lc * 32;
    const float* vtn = g_vt + (n * LQ + lbase) * EE;
#pragma unroll
    for (int i = 0; i < 8; i++) {
        int idx = i * 256 + tid;
        sv[idx >> 6][idx & 63] = vtn[idx];
    }
    __syncthreads();

    // Micro-tile: 2 l-rows x 4 e-cols per thread
    const int r0 = (tid >> 4) * 2;   // 0..30
    const int e0 = (tid & 15) * 4;   // 0..60

    float a00 = 0.f, a01 = 0.f, a02 = 0.f, a03 = 0.f;
    float a10 = 0.f, a11 = 0.f, a12 = 0.f, a13 = 0.f;
#pragma unroll
    for (int k = 0; k < 64; k++) {
        float v0 = sv[r0][k];
        float v1 = sv[r0 + 1][k];
        float4 m = *(const float4*)&sMt[k][e0];
        a00 += v0 * m.x; a01 += v0 * m.y; a02 += v0 * m.z; a03 += v0 * m.w;
        a10 += v1 * m.x; a11 += v1 * m.y; a12 += v1 * m.z; a13 += v1 * m.w;
    }
    // add fc bias before LN
    float b0v = sb[e0], b1v = sb[e0 + 1], b2v = sb[e0 + 2], b3v = sb[e0 + 3];
    a00 += b0v; a01 += b1v; a02 += b2v; a03 += b3v;
    a10 += b0v; a11 += b1v; a12 += b2v; a13 += b3v;

    // LN stats: reduce over the 16 lanes that share a row-pair (offsets 1..8)
    float s0 = (a00 + a01) + (a02 + a03);
    float q0 = (a00 * a00 + a01 * a01) + (a02 * a02 + a03 * a03);
    float s1 = (a10 + a11) + (a12 + a13);
    float q1 = (a10 * a10 + a11 * a11) + (a12 * a12 + a13 * a13);
#pragma unroll
    for (int off = 8; off; off >>= 1) {
        s0 += __shfl_xor_sync(0xffffffffu, s0, off);
        q0 += __shfl_xor_sync(0xffffffffu, q0, off);
        s1 += __shfl_xor_sync(0xffffffffu, s1, off);
        q1 += __shfl_xor_sync(0xffffffffu, q1, off);
    }
    float mu0 = s0 * (1.0f / 64.0f);
    float var0 = q0 * (1.0f / 64.0f) - mu0 * mu0;
    float ri0 = rsqrtf(var0 + 1e-5f);
    float mu1 = s1 * (1.0f / 64.0f);
    float var1 = q1 * (1.0f / 64.0f) - mu1 * mu1;
    float ri1 = rsqrtf(var1 + 1e-5f);

    float w0 = sw[e0], w1 = sw[e0 + 1], w2 = sw[e0 + 2], w3 = sw[e0 + 3];
    float g0 = sbeta[e0], g1 = sbeta[e0 + 1], g2 = sbeta[e0 + 2], g3 = sbeta[e0 + 3];

    *(float4*)&sy[r0][e0] = make_float4((a00 - mu0) * ri0 * w0 + g0,
                                        (a01 - mu0) * ri0 * w1 + g1,
                                        (a02 - mu0) * ri0 * w2 + g2,
                                        (a03 - mu0) * ri0 * w3 + g3);
    *(float4*)&sy[r0 + 1][e0] = make_float4((a10 - mu1) * ri1 * w0 + g0,
                                            (a11 - mu1) * ri1 * w1 + g1,
                                            (a12 - mu1) * ri1 * w2 + g2,
                                            (a13 - mu1) * ri1 * w3 + g3);
    __syncthreads();

    // write h = 0 slice only (coalesced STG.128)
    const float4* sy4 = (const float4*)sy;
    float4* dst = (float4*)out + n * 4096 + lc * 512 + tid;
    dst[0] = sy4[tid];
    dst[256] = sy4[tid + 256];
}

// ---------------------------------------------------------------------------
// K4: broadcast h=0 slice (4 MB) to h = 1..63 (252 MB of streaming writes).
// grid: 1024 blocks, each owns a 4 KB contiguous segment; one float4 per
// thread held in a register; 63 independent STG.128 per thread.
// ~7 CTAs/SM -> ~56 warps/SM of outstanding stores (R6 had only ~14).
// ---------------------------------------------------------------------------
__global__ void __launch_bounds__(256) k_bcast(float* __restrict__ out) {
    const int tid = threadIdx.x;
    const size_t segOff4 = (size_t)blockIdx.x * 256;   // float4 units (4KB/block)
    float4 v = ((const float4*)out)[segOff4 + tid];
    float4* dst = (float4*)out + segOff4 + tid;
    const size_t hstride4 = (size_t)NB * LQ * EE / 4;  // 262144 float4 = 4 MB
#pragma unroll 9
    for (int h = 1; h < HH; h++) {
        __stcs(dst + (size_t)h * hstride4, v);
    }
}

// ---------------------------------------------------------------------------
extern "C" void kernel_launch(void* const* d_in, const int* in_sizes, int n_in,
                              void* d_out, int out_size) {
    const float* values = (const float*)d_in[0];
    const float* keys   = (const float*)d_in[1];
    const float* query  = (const float*)d_in[2];
    const float* W      = (const float*)d_in[3];
    const float* b      = (const float*)d_in[4];
    const float* lnw    = (const float*)d_in[5];
    const float* lnb    = (const float*)d_in[6];
    float* out = (float*)d_out;

    k_front<<<384, 256>>>(values, query, keys);
    k_M<<<64, 256>>>(W);
    k_compute<<<512, 256>>>(b, lnw, lnb, out);
    k_bcast<<<1024, 256>>>(out);
}